// round 17
// baseline (speedup 1.0000x reference)
#include <cuda_runtime.h>
#include <cstdint>

#define N_NODES 50000
#define N_EDGES 800000
#define D 64
#define N_LAYERS 3

// Scratch (allocation-free rule: __device__ globals). float4 => 16B aligned.
// g_cnt: zero-initialized at module load; reorder_kernel re-zeroes it each
// call, so every kernel_launch sees cnt == 0 (deterministic).
__device__ float4 g_buf0[N_NODES * D / 4];
__device__ float4 g_buf1[N_NODES * D / 4];
__device__ float4 g_agg [N_NODES * D / 4];
__device__ int    g_cnt   [N_NODES];
__device__ int    g_rowptr[N_NODES + 1];
__device__ int    g_cursor[N_NODES];
__device__ int    g_col   [N_EDGES];

// ---------------------------------------------------------------------------
// tf32 helpers
// ---------------------------------------------------------------------------
__device__ __forceinline__ unsigned f2tf32(float f) {
    unsigned r;
    asm("cvt.rna.tf32.f32 %0, %1;" : "=r"(r) : "f"(f));
    return r;
}
__device__ __forceinline__ void tf32_split(float v, float& hi, float& lo) {
    unsigned h = f2tf32(v);
    hi = __uint_as_float(h);
    lo = __uint_as_float(f2tf32(v - __uint_as_float(h)));
}
// D = A(16x8,tf32) * B(8x8,tf32) + D, fp32 accum
__device__ __forceinline__ void mma_tf32(float c[4], const unsigned a[4],
                                         const unsigned b[2]) {
    asm volatile(
        "mma.sync.aligned.m16n8k8.row.col.f32.tf32.tf32.f32 "
        "{%0,%1,%2,%3}, {%4,%5,%6,%7}, {%8,%9}, {%0,%1,%2,%3};\n"
        : "+f"(c[0]), "+f"(c[1]), "+f"(c[2]), "+f"(c[3])
        : "r"(a[0]), "r"(a[1]), "r"(a[2]), "r"(a[3]), "r"(b[0]), "r"(b[1]));
}

// ---------------------------------------------------------------------------
// idx 0: in-degree histogram (cnt must be 0 on entry)
// ---------------------------------------------------------------------------
__global__ void hist_kernel(const int* __restrict__ dst, int* __restrict__ cnt) {
    int e = blockIdx.x * blockDim.x + threadIdx.x;
    if (e < N_EDGES) atomicAdd(&cnt[dst[e]], 1);
}

// ---------------------------------------------------------------------------
// idx 1: exclusive prefix sum (single block, 1024 threads)
// ---------------------------------------------------------------------------
#define SCAN_THREADS 1024
#define CHUNK ((N_NODES + SCAN_THREADS - 1) / SCAN_THREADS)   // 49

__global__ void __launch_bounds__(SCAN_THREADS) scan_kernel(
        const int* __restrict__ cnt,
        int* __restrict__ rowptr,
        int* __restrict__ cursor) {
    __shared__ int s[SCAN_THREADS];
    const int t = threadIdx.x;
    const int base = t * CHUNK;

    int total = 0;
    #pragma unroll 7
    for (int i = 0; i < CHUNK; i++) {
        int idx = base + i;
        if (idx < N_NODES) total += cnt[idx];
    }
    s[t] = total;
    __syncthreads();

    #pragma unroll
    for (int off = 1; off < SCAN_THREADS; off <<= 1) {
        int v = (t >= off) ? s[t - off] : 0;
        __syncthreads();
        s[t] += v;
        __syncthreads();
    }
    int run = (t == 0) ? 0 : s[t - 1];

    #pragma unroll 7
    for (int i = 0; i < CHUNK; i++) {
        int idx = base + i;
        if (idx < N_NODES) {
            rowptr[idx] = run;
            cursor[idx] = run;
            run += cnt[idx];
        }
    }
    if (t == 0) rowptr[N_NODES] = N_EDGES;
}

// ---------------------------------------------------------------------------
// idx 2: reorder; also re-zeroes cnt for the next call
// ---------------------------------------------------------------------------
__global__ void reorder_kernel(const int* __restrict__ src,
                               const int* __restrict__ dst,
                               int* __restrict__ cursor,
                               int* __restrict__ col,
                               int* __restrict__ cnt) {
    int e = blockIdx.x * blockDim.x + threadIdx.x;
    if (e < N_NODES) cnt[e] = 0;
    if (e >= N_EDGES) return;
    int p = atomicAdd(&cursor[dst[e]], 1);
    col[p] = src[e];
}

// ---------------------------------------------------------------------------
// agg[n] = sum_{e in in(n)} x[col[e]]  (21 us measured, stable)
// ---------------------------------------------------------------------------
__global__ void __launch_bounds__(256) agg_kernel(
        const float4* __restrict__ x4,
        const int* __restrict__ rowptr,
        const int* __restrict__ col,
        float4* __restrict__ agg4) {
    const int n    = blockIdx.x * 32 + (threadIdx.x >> 3);
    const int lane = threadIdx.x & 7;
    if (n >= N_NODES) return;
    const int beg = rowptr[n];
    const int end = rowptr[n + 1];

    float4 a0 = make_float4(0.f, 0.f, 0.f, 0.f);
    float4 a1 = make_float4(0.f, 0.f, 0.f, 0.f);

    int e = beg;
    for (; e + 4 <= end; e += 4) {
        int s0 = col[e], s1 = col[e + 1], s2 = col[e + 2], s3 = col[e + 3];
        const float4* p0 = x4 + (size_t)s0 * 16 + lane;
        const float4* p1 = x4 + (size_t)s1 * 16 + lane;
        const float4* p2 = x4 + (size_t)s2 * 16 + lane;
        const float4* p3 = x4 + (size_t)s3 * 16 + lane;
        float4 v00 = __ldg(p0),     v01 = __ldg(p0 + 8);
        float4 v10 = __ldg(p1),     v11 = __ldg(p1 + 8);
        float4 v20 = __ldg(p2),     v21 = __ldg(p2 + 8);
        float4 v30 = __ldg(p3),     v31 = __ldg(p3 + 8);
        a0.x += v00.x + v10.x + v20.x + v30.x;
        a0.y += v00.y + v10.y + v20.y + v30.y;
        a0.z += v00.z + v10.z + v20.z + v30.z;
        a0.w += v00.w + v10.w + v20.w + v30.w;
        a1.x += v01.x + v11.x + v21.x + v31.x;
        a1.y += v01.y + v11.y + v21.y + v31.y;
        a1.z += v01.z + v11.z + v21.z + v31.z;
        a1.w += v01.w + v11.w + v21.w + v31.w;
    }
    for (; e < end; e++) {
        const float4* p = x4 + (size_t)col[e] * 16 + lane;
        float4 v0 = __ldg(p), v1 = __ldg(p + 8);
        a0.x += v0.x; a0.y += v0.y; a0.z += v0.z; a0.w += v0.w;
        a1.x += v1.x; a1.y += v1.y; a1.z += v1.z; a1.w += v1.w;
    }
    agg4[(size_t)n * 16 + lane]     = a0;
    agg4[(size_t)n * 16 + 8 + lane] = a1;
}

// ---------------------------------------------------------------------------
// Single-weight tensor-core GEMM part:
//   accumulate=0: out = in @ W + bias          (self part; no relu)
//   accumulate=1: out = relu?(out + in @ W)    (msg part; bias=null)
// Operands pre-split into tf32 hi/lo in SMEM during the fills -> the
// mainloop is pure LDS + MMA (zero cvt on the critical path).
// Block 256 thr / 8 warps, tile 128(M) x 64(N); warp = 32x32.
// All fragment LDS conflict-free via stride 68 (bank = 4g + tid4).
// ---------------------------------------------------------------------------
#define TILE_ROWS 128
#define XSTRIDE 68
#define SMEM_FLOATS (2 * TILE_ROWS * XSTRIDE + 2 * 64 * XSTRIDE)

__global__ void __launch_bounds__(256) part_gemm_kernel(
        const float* __restrict__ in,
        const float* __restrict__ W,
        const float* __restrict__ bias,      // null => no bias
        float* __restrict__ out,
        int accumulate,
        int apply_relu) {
    extern __shared__ float sm[];
    float* sMh = sm;                          // [128][68] tf32-hi of in-tile
    float* sMl = sMh + TILE_ROWS * XSTRIDE;   // [128][68] tf32-lo
    float* sWh = sMl + TILE_ROWS * XSTRIDE;   // [64][68]  W^T tf32-hi (n-major)
    float* sWl = sWh + 64 * XSTRIDE;          // [64][68]  W^T tf32-lo

    const int tid     = threadIdx.x;
    const int rowbase = blockIdx.x * TILE_ROWS;
    const float4* in4 = reinterpret_cast<const float4*>(in);

    // ---- fill input tile, splitting to hi/lo once ----
    for (int i = tid; i < TILE_ROWS * 16; i += 256) {
        int r = i >> 4;
        int c = i & 15;
        int grow = rowbase + r;
        float4 v = make_float4(0.f, 0.f, 0.f, 0.f);
        if (grow < N_NODES) v = in4[(size_t)grow * 16 + c];
        float4 h, l;
        tf32_split(v.x, h.x, l.x);
        tf32_split(v.y, h.y, l.y);
        tf32_split(v.z, h.z, l.z);
        tf32_split(v.w, h.w, l.w);
        *reinterpret_cast<float4*>(sMh + r * XSTRIDE + c * 4) = h;
        *reinterpret_cast<float4*>(sMl + r * XSTRIDE + c * 4) = l;
    }
    // ---- fill transposed weights, splitting once: sW[n][k] = W[k][n] ----
    for (int i = tid; i < 64 * 64; i += 256) {
        int k = i >> 6;
        int n = i & 63;
        float h, l;
        tf32_split(W[k * 64 + n], h, l);
        sWh[n * XSTRIDE + k] = h;
        sWl[n * XSTRIDE + k] = l;
    }
    __syncthreads();

    const int w      = tid >> 5;
    const int lane   = tid & 31;
    const int g      = lane >> 2;     // groupID (0..7)
    const int tid4   = lane & 3;      // threadID_in_group (0..3)
    const int warp_m = w >> 1;        // 0..3 -> row block warp_m*32
    const int warp_n = w & 1;         // 0..1 -> col block warp_n*32

    float cacc[8][4];
    #pragma unroll
    for (int i = 0; i < 8; i++)
        #pragma unroll
        for (int j = 0; j < 4; j++) cacc[i][j] = 0.f;

    #pragma unroll
    for (int k0 = 0; k0 < 64; k0 += 8) {
        unsigned ah[2][4], al[2][4];
        #pragma unroll
        for (int mt = 0; mt < 2; mt++) {
            const int rb = warp_m * 32 + mt * 16;
            const float* ph = sMh + (rb + g) * XSTRIDE + k0 + tid4;
            const float* pl = sMl + (rb + g) * XSTRIDE + k0 + tid4;
            ah[mt][0] = __float_as_uint(ph[0]);
            ah[mt][1] = __float_as_uint(ph[8 * XSTRIDE]);
            ah[mt][2] = __float_as_uint(ph[4]);
            ah[mt][3] = __float_as_uint(ph[8 * XSTRIDE + 4]);
            al[mt][0] = __float_as_uint(pl[0]);
            al[mt][1] = __float_as_uint(pl[8 * XSTRIDE]);
            al[mt][2] = __float_as_uint(pl[4]);
            al[mt][3] = __float_as_uint(pl[8 * XSTRIDE + 4]);
        }
        unsigned bh[4][2], bl[4][2];
        #pragma unroll
        for (int nt = 0; nt < 4; nt++) {
            const int nc = warp_n * 32 + nt * 8 + g;
            const float* ph = sWh + nc * XSTRIDE + k0 + tid4;
            const float* pl = sWl + nc * XSTRIDE + k0 + tid4;
            bh[nt][0] = __float_as_uint(ph[0]);
            bh[nt][1] = __float_as_uint(ph[4]);
            bl[nt][0] = __float_as_uint(pl[0]);
            bl[nt][1] = __float_as_uint(pl[4]);
        }
        #pragma unroll
        for (int mt = 0; mt < 2; mt++)
            #pragma unroll
            for (int nt = 0; nt < 4; nt++) {
                float* c = cacc[mt * 4 + nt];
                mma_tf32(c, ah[mt], bh[nt]);
                mma_tf32(c, al[mt], bh[nt]);
                mma_tf32(c, ah[mt], bl[nt]);
            }
    }

    // ---- epilogue ----
    #pragma unroll
    for (int mt = 0; mt < 2; mt++) {
        #pragma unroll
        for (int nt = 0; nt < 4; nt++) {
            const float* c = cacc[mt * 4 + nt];
            const int colb = warp_n * 32 + nt * 8 + tid4 * 2;
            const int r0 = rowbase + warp_m * 32 + mt * 16 + g;
            const int r1 = r0 + 8;
            float2 v0 = make_float2(c[0], c[1]);
            float2 v1 = make_float2(c[2], c[3]);
            if (bias) {
                const float2 bv = *reinterpret_cast<const float2*>(bias + colb);
                v0.x += bv.x; v0.y += bv.y;
                v1.x += bv.x; v1.y += bv.y;
            }
            if (accumulate) {
                if (r0 < N_NODES) {
                    float2 p = *reinterpret_cast<const float2*>(out + (size_t)r0 * D + colb);
                    v0.x += p.x; v0.y += p.y;
                }
                if (r1 < N_NODES) {
                    float2 p = *reinterpret_cast<const float2*>(out + (size_t)r1 * D + colb);
                    v1.x += p.x; v1.y += p.y;
                }
            }
            if (apply_relu) {
                v0.x = fmaxf(v0.x, 0.f); v0.y = fmaxf(v0.y, 0.f);
                v1.x = fmaxf(v1.x, 0.f); v1.y = fmaxf(v1.y, 0.f);
            }
            if (r0 < N_NODES)
                *reinterpret_cast<float2*>(out + (size_t)r0 * D + colb) = v0;
            if (r1 < N_NODES)
                *reinterpret_cast<float2*>(out + (size_t)r1 * D + colb) = v1;
        }
    }
}

// ---------------------------------------------------------------------------
// Launch: hist(0), scan(1), reorder(2),
//         per layer: self_gemm (idx 3 for layer 0 <- ncu), agg, msg_gemm.
// ---------------------------------------------------------------------------
extern "C" void kernel_launch(void* const* d_in, const int* in_sizes, int n_in,
                              void* d_out, int out_size) {
    (void)in_sizes; (void)n_in; (void)out_size;

    const float* x0    = (const float*)d_in[0];
    const int*   ei    = (const int*)d_in[1];      // int32 (JAX x64 disabled)
    const float* Wmsg  = (const float*)d_in[2];    // [3][64][64]
    const float* Wself = (const float*)d_in[3];    // [3][64][64]
    const float* bias  = (const float*)d_in[4];    // [3][64]
    float*       out   = (float*)d_out;

    const int* src = ei;
    const int* dst = ei + N_EDGES;

    float4 *buf0, *buf1, *agg;
    int *cnt, *rowptr, *cursor, *col;
    cudaGetSymbolAddress((void**)&buf0,   g_buf0);
    cudaGetSymbolAddress((void**)&buf1,   g_buf1);
    cudaGetSymbolAddress((void**)&agg,    g_agg);
    cudaGetSymbolAddress((void**)&cnt,    g_cnt);
    cudaGetSymbolAddress((void**)&rowptr, g_rowptr);
    cudaGetSymbolAddress((void**)&cursor, g_cursor);
    cudaGetSymbolAddress((void**)&col,    g_col);

    static bool attr_set = false;
    const int smem_bytes = SMEM_FLOATS * (int)sizeof(float);
    if (!attr_set) {
        cudaFuncSetAttribute(part_gemm_kernel,
                             cudaFuncAttributeMaxDynamicSharedMemorySize, smem_bytes);
        attr_set = true;
    }

    // ---- CSR build ----
    hist_kernel<<<(N_EDGES + 255) / 256, 256>>>(dst, cnt);                      // 0
    scan_kernel<<<1, SCAN_THREADS>>>(cnt, rowptr, cursor);                      // 1
    reorder_kernel<<<(N_EDGES + 255) / 256, 256>>>(src, dst, cursor, col, cnt); // 2

    // ---- Layers ----
    const float* cur[N_LAYERS]  = { x0, (const float*)buf0, (const float*)buf1 };
    float*       next[N_LAYERS] = { (float*)buf0, (float*)buf1, out };

    const int agg_blocks  = (N_NODES + 31) / 32;                    // 1563
    const int gemm_blocks = (N_NODES + TILE_ROWS - 1) / TILE_ROWS;  // 391

    for (int layer = 0; layer < N_LAYERS; layer++) {
        // self part first (no agg dependency) -> layer 0 lands at idx 3
        part_gemm_kernel<<<gemm_blocks, 256, smem_bytes>>>(
            cur[layer],
            Wself + (size_t)layer * D * D,
            bias  + (size_t)layer * D,
            next[layer],
            /*accumulate=*/0, /*relu=*/0);
        agg_kernel<<<agg_blocks, 256>>>(
            (const float4*)cur[layer], rowptr, col, agg);
        part_gemm_kernel<<<gemm_blocks, 256, smem_bytes>>>(
            (const float*)agg,
            Wmsg + (size_t)layer * D * D,
            /*bias=*/nullptr,
            next[layer],
            /*accumulate=*/1, /*relu=*/layer < N_LAYERS - 1 ? 1 : 0);
    }
}